// round 10
// baseline (speedup 1.0000x reference)
#include <cuda_runtime.h>

// Problem constants
#define HDIM   512
#define BATCH  2
#define SEQ    128
#define DSRC   768
#define NTOK   (BATCH * SEQ)   // 256
#define NITER  30
#define NBLK   16              // 512 / 32 sorted blocks
#define MINIT  6               // minimum iterations before early exit
#define DTOL   2.0e-5f         // per-iteration dual-change tolerance (log2)

// -(SCALE/REG) * log2(e) = -5000 * 1.4426950408889634
#define NEGC  (-7213.4752044448170f)
#define CPOS  (7213.4752044448170f)
// -log2(H)
#define LOGMARG2 (-9.0f)
// cutoff: drop terms with tau < -TW (mass < 512*2^-60 of a row/col sum)
#define TW 60.0f

// Scratch (static device globals; no runtime allocation allowed)
__device__ float g_src[NTOK * HDIM];            // 512 KB
__device__ float g_sumP[BATCH * HDIM * HDIM];   // 2 MB

__device__ __forceinline__ float ex2(float x) {
    float y; asm("ex2.approx.f32 %0, %1;" : "=f"(y) : "f"(x)); return y;
}
__device__ __forceinline__ float lg2(float x) {
    float y; asm("lg2.approx.f32 %0, %1;" : "=f"(y) : "f"(x)); return y;
}

// ---------------------------------------------------------------------------
// Stage 0: zero plan accumulator AND d_out (harness poisons it; out_kernel
// accumulates with atomics). Graph replays -> must run every launch.
// ---------------------------------------------------------------------------
#define NZ_P   (BATCH * HDIM * HDIM / 4)   // 131072 float4
#define NZ_OUT (NTOK * HDIM / 4)           // 32768 float4
__global__ void zero_kernel(float* __restrict__ out) {
    int i = blockIdx.x * blockDim.x + threadIdx.x;
    float4 z = make_float4(0.f, 0.f, 0.f, 0.f);
    if (i < NZ_P) reinterpret_cast<float4*>(g_sumP)[i] = z;
    else          reinterpret_cast<float4*>(out)[i - NZ_P] = z;
}

// ---------------------------------------------------------------------------
// Stage 1: src[tok, h] = X[tok] . W[h] + b[h]   (4 tokens per CTA)
// ---------------------------------------------------------------------------
#define TPG 4
__global__ void __launch_bounds__(HDIM) src_kernel(
    const float* __restrict__ X, const float* __restrict__ W,
    const float* __restrict__ b)
{
    const int tok0 = blockIdx.x * TPG;
    __shared__ __align__(16) float xs[TPG][DSRC];   // 12 KB
    for (int idx = threadIdx.x; idx < TPG * DSRC; idx += HDIM)
        xs[idx / DSRC][idx % DSRC] = X[tok0 * DSRC + idx];
    __syncthreads();

    const int h = threadIdx.x;
    const float4* wr = reinterpret_cast<const float4*>(W + (size_t)h * DSRC);
    float acc0 = 0.f, acc1 = 0.f, acc2 = 0.f, acc3 = 0.f;
#pragma unroll 4
    for (int q = 0; q < DSRC / 4; q++) {
        float4 w4 = wr[q];
        float4 x0 = reinterpret_cast<const float4*>(xs[0])[q];
        float4 x1 = reinterpret_cast<const float4*>(xs[1])[q];
        float4 x2 = reinterpret_cast<const float4*>(xs[2])[q];
        float4 x3 = reinterpret_cast<const float4*>(xs[3])[q];
        acc0 = fmaf(w4.x, x0.x, acc0); acc0 = fmaf(w4.y, x0.y, acc0);
        acc0 = fmaf(w4.z, x0.z, acc0); acc0 = fmaf(w4.w, x0.w, acc0);
        acc1 = fmaf(w4.x, x1.x, acc1); acc1 = fmaf(w4.y, x1.y, acc1);
        acc1 = fmaf(w4.z, x1.z, acc1); acc1 = fmaf(w4.w, x1.w, acc1);
        acc2 = fmaf(w4.x, x2.x, acc2); acc2 = fmaf(w4.y, x2.y, acc2);
        acc2 = fmaf(w4.z, x2.z, acc2); acc2 = fmaf(w4.w, x2.w, acc2);
        acc3 = fmaf(w4.x, x3.x, acc3); acc3 = fmaf(w4.y, x3.y, acc3);
        acc3 = fmaf(w4.z, x3.z, acc3); acc3 = fmaf(w4.w, x3.w, acc3);
    }
    float bh = b[h];
    g_src[(tok0 + 0) * HDIM + h] = acc0 + bh;
    g_src[(tok0 + 1) * HDIM + h] = acc1 + bh;
    g_src[(tok0 + 2) * HDIM + h] = acc2 + bh;
    g_src[(tok0 + 3) * HDIM + h] = acc3 + bh;
}

// ---------------------------------------------------------------------------
// Binary search over sorted .x of a float2 array (for u-init only).
// ---------------------------------------------------------------------------
__device__ __forceinline__ int lbound(const float2* __restrict__ A, float x) {
    int lo = 0, hi = HDIM;
    while (lo < hi) { int m = (lo + hi) >> 1; if (A[m].x < x) lo = m + 1; else hi = m; }
    return lo;
}

// ---------------------------------------------------------------------------
// One culled half-pass sum: a = sum over qualifying elements of
//   2^( NEGC*(arr[c].x - own)^2 + arr[c].y + sh )
// Blocks of 32 sorted elements are skipped when even their best case
// ( max dual in block, closest boundary distance ) stays below -TW.
// ---------------------------------------------------------------------------
__device__ __forceinline__ float culled_sum(const float2* __restrict__ arr,
                                            const float* __restrict__ blkMax,
                                            float own, float sh)
{
    float a = 1e-30f;
#pragma unroll 1
    for (int b = 0; b < NBLK; b++) {
        float lo = arr[32 * b].x;
        float hi = arr[32 * b + 31].x;
        float dd = fmaxf(fmaxf(lo - own, own - hi), 0.0f);
        if (fmaf(dd * dd, NEGC, blkMax[b] + sh) >= -TW) {
            float aa = 0.f, ab = 0.f;
#pragma unroll
            for (int c = 32 * b; c < 32 * b + 32; c += 2) {
                float2 q0 = arr[c];
                float2 q1 = arr[c + 1];
                float d0 = q0.x - own;
                float d1 = q1.x - own;
                aa += ex2(fmaf(d0 * d0, NEGC, q0.y + sh));
                ab += ex2(fmaf(d1 * d1, NEGC, q1.y + sh));
            }
            a += aa + ab;
        }
    }
    return a;
}

// ---------------------------------------------------------------------------
// Stage 2: block-culled per-token base-2 log-domain Sinkhorn + early exit.
// s,t bitonic-sorted with index payloads. Thread tid owns sorted row tid
// (t side, dual u) and sorted column tid (s side, dual v). Warp w == sorted
// block w; after each half-pass it publishes blkMax (max dual in block).
// Early exit: when the max per-iteration dual change (u and v combined)
// drops below DTOL, remaining iterations change P by < ~1e-4 relative
// (geometric tail) -> terminate. Uniform branch, deterministic per input.
// ---------------------------------------------------------------------------
__global__ void __launch_bounds__(512, 2) sinkhorn_kernel(
    const float* __restrict__ Y)
{
    const int tok  = blockIdx.x;
    const int bat  = tok >> 7;
    const int tid  = threadIdx.x;
    const int lane = tid & 31;
    const int warp = tid >> 5;

    __shared__ __align__(16) float2 SV[HDIM];   // (sorted s value, v dual)
    __shared__ __align__(16) float2 TU[HDIM];   // (sorted t value, u dual)
    __shared__ int   sIdx[HDIM];                // sorted pos -> original col
    __shared__ int   tIdx[HDIM];                // sorted pos -> original row
    __shared__ float blkMaxV[NBLK];             // per-block max of v (s side)
    __shared__ float blkMaxU[NBLK];             // per-block max of u (t side)
    __shared__ float dMax[NBLK];                // per-warp max dual change

    SV[tid] = make_float2(g_src[tok * HDIM + tid], 0.f);
    TU[tid] = make_float2(Y[tok * HDIM + tid],     0.f);
    sIdx[tid] = tid;
    tIdx[tid] = tid;
    if (tid < NBLK) blkMaxV[tid] = 0.f;
    __syncthreads();

    // joint bitonic sort of s-array and t-array (values + index payloads)
    float* svx = &SV[0].x;
    float* tux = &TU[0].x;
    for (int k = 2; k <= HDIM; k <<= 1) {
        for (int j = k >> 1; j > 0; j >>= 1) {
            int ixj = tid ^ j;
            if (ixj > tid) {
                bool up = ((tid & k) == 0);
                float a = svx[2 * tid], b2 = svx[2 * ixj];
                if (up ? (a > b2) : (a < b2)) {
                    svx[2 * tid] = b2; svx[2 * ixj] = a;
                    int ti = sIdx[tid]; sIdx[tid] = sIdx[ixj]; sIdx[ixj] = ti;
                }
                float c = tux[2 * tid], d2 = tux[2 * ixj];
                if (up ? (c > d2) : (c < d2)) {
                    tux[2 * tid] = d2; tux[2 * ixj] = c;
                    int ti = tIdx[tid]; tIdx[tid] = tIdx[ixj]; tIdx[ixj] = ti;
                }
            }
            __syncthreads();
        }
    }

    const float t_own = TU[tid].x;
    const float s_own = SV[tid].x;
    const int   jorig = tIdx[tid];

    // init u via nearest sorted s neighbor: u = -9 + C*d_nn^2
    float u_own;
    {
        int p = lbound(SV, t_own);
        float dn = 3.402823466e+38f;
        if (p < HDIM) dn = fabsf(SV[p].x - t_own);
        if (p > 0)    dn = fminf(dn, fabsf(SV[p - 1].x - t_own));
        u_own = LOGMARG2 + CPOS * dn * dn;
    }
    float v_own = 0.f;

    for (int it = 0; it < NITER; it++) {
        // ---- u-pass: culled sum over sorted s blocks ----
        float du = lg2(culled_sum(SV, blkMaxV, t_own, u_own + 9.0f));
        u_own -= du;
        TU[tid].y = u_own;
        {
            float m = u_own;
#pragma unroll
            for (int o = 16; o; o >>= 1)
                m = fmaxf(m, __shfl_xor_sync(0xffffffffu, m, o));
            if (lane == 0) blkMaxU[warp] = m;
        }
        __syncthreads();

        // ---- v-pass: culled sum over sorted t blocks ----
        float dv = lg2(culled_sum(TU, blkMaxU, s_own, v_own + 9.0f));
        v_own -= dv;
        SV[tid].y = v_own;
        {
            float m = v_own;
            float dm = fmaxf(fabsf(du), fabsf(dv));
#pragma unroll
            for (int o = 16; o; o >>= 1) {
                m  = fmaxf(m,  __shfl_xor_sync(0xffffffffu, m,  o));
                dm = fmaxf(dm, __shfl_xor_sync(0xffffffffu, dm, o));
            }
            if (lane == 0) { blkMaxV[warp] = m; dMax[warp] = dm; }
        }
        __syncthreads();

        // ---- convergence check (uniform across CTA) ----
        if (it >= MINIT) {
            float mx = dMax[0];
#pragma unroll
            for (int i = 1; i < NBLK; i++) mx = fmaxf(mx, dMax[i]);
            if (mx < DTOL) break;
        }
    }

    // ---- Plan: P[jorig, iorig] = 2^(tau - 9), tau = -C d^2 + v + u + 9 ----
    {
        float* rowdst = g_sumP + (size_t)bat * HDIM * HDIM + (size_t)jorig * HDIM;
        const float sh = u_own + 9.0f;
#pragma unroll 1
        for (int b = 0; b < NBLK; b++) {
            float lo = SV[32 * b].x;
            float hi = SV[32 * b + 31].x;
            float dd = fmaxf(fmaxf(lo - t_own, t_own - hi), 0.0f);
            if (fmaf(dd * dd, NEGC, blkMaxV[b] + sh) >= -31.0f) {
#pragma unroll 4
                for (int c = 32 * b; c < 32 * b + 32; c++) {
                    float2 q = SV[c];
                    float d = q.x - t_own;
                    float tau = fmaf(d * d, NEGC, q.y + sh);
                    if (tau > -31.f) atomicAdd(rowdst + sIdx[c], ex2(tau - 9.0f));
                }
            }
        }
    }
}

// ---------------------------------------------------------------------------
// Stage 3: out[tok, k] += sum_{h in slice} src[tok,h]*(sumP[b,h,k]*2000
//                                                      + delta[h,k])
// Grid (16 token-groups of 16, 16 h-slices of 32). 256 CTAs, 256 threads.
// ---------------------------------------------------------------------------
#define OT_TOK 16
#define OT_H   32
__global__ void __launch_bounds__(256) out_kernel(
    const float* __restrict__ delta, float* __restrict__ out)
{
    const int tok0 = blockIdx.x * OT_TOK;
    const int h0   = blockIdx.y * OT_H;
    const int bat  = tok0 >> 7;       // OT_TOK divides SEQ -> no straddle
    const int k2   = threadIdx.x;     // float2 column index (0..255)

    __shared__ float sr[OT_TOK][OT_H];   // 2 KB
    for (int idx = threadIdx.x; idx < OT_TOK * OT_H; idx += 256)
        sr[idx / OT_H][idx % OT_H] = g_src[(tok0 + idx / OT_H) * HDIM + h0 + idx % OT_H];
    __syncthreads();

    const float2* P2 = reinterpret_cast<const float2*>(
        g_sumP + (size_t)bat * HDIM * HDIM);
    const float2* D2 = reinterpret_cast<const float2*>(delta);

    float a0[OT_TOK], a1[OT_TOK];
#pragma unroll
    for (int t = 0; t < OT_TOK; t++) { a0[t] = 0.f; a1[t] = 0.f; }

#pragma unroll 4
    for (int h = 0; h < OT_H; h++) {
        float2 p = __ldg(&P2[(h0 + h) * 256 + k2]);
        float2 d = __ldg(&D2[(h0 + h) * 256 + k2]);
        float pv0 = fmaf(p.x, 2000.0f, d.x);
        float pv1 = fmaf(p.y, 2000.0f, d.y);
#pragma unroll
        for (int t = 0; t < OT_TOK; t++) {
            float s = sr[t][h];
            a0[t] = fmaf(s, pv0, a0[t]);
            a1[t] = fmaf(s, pv1, a1[t]);
        }
    }
#pragma unroll
    for (int t = 0; t < OT_TOK; t++) {
        atomicAdd(&out[(tok0 + t) * HDIM + 2 * k2],     a0[t]);
        atomicAdd(&out[(tok0 + t) * HDIM + 2 * k2 + 1], a1[t]);
    }
}

// ---------------------------------------------------------------------------
extern "C" void kernel_launch(void* const* d_in, const int* in_sizes, int n_in,
                              void* d_out, int out_size)
{
    const float* X     = (const float*)d_in[0];  // (2,128,768)
    const float* Y     = (const float*)d_in[1];  // (2,128,512)
    const float* W     = (const float*)d_in[2];  // (512,768)
    const float* b     = (const float*)d_in[3];  // (512)
    const float* delta = (const float*)d_in[4];  // (512,512)
    float* out = (float*)d_out;                  // (2,128,512)

    zero_kernel<<<(NZ_P + NZ_OUT) / 256, 256>>>(out);
    src_kernel<<<NTOK / TPG, HDIM>>>(X, W, b);
    sinkhorn_kernel<<<NTOK, 512>>>(Y);
    dim3 ogrid(NTOK / OT_TOK, HDIM / OT_H);
    out_kernel<<<ogrid, 256>>>(delta, out);
}

// round 11
// speedup vs baseline: 1.1308x; 1.1308x over previous
#include <cuda_runtime.h>

// Problem constants
#define HDIM   512
#define BATCH  2
#define SEQ    128
#define DSRC   768
#define NTOK   (BATCH * SEQ)   // 256
#define NITER  30
#define NBLK   16              // 512 / 32 sorted blocks

// -(SCALE/REG) * log2(e) = -5000 * 1.4426950408889634
#define NEGC  (-7213.4752044448170f)
#define CPOS  (7213.4752044448170f)
// -log2(H)
#define LOGMARG2 (-9.0f)
// cutoff: drop terms with tau < -TW (mass < 512*2^-40 of a row/col sum,
// below the reference's own f32 summation noise)
#define TW 40.0f

typedef unsigned long long ull;

// Scratch (static device globals; no runtime allocation allowed)
__device__ float g_src[NTOK * HDIM];            // 512 KB
__device__ float g_sumP[BATCH * HDIM * HDIM];   // 2 MB

__device__ __forceinline__ float ex2(float x) {
    float y; asm("ex2.approx.f32 %0, %1;" : "=f"(y) : "f"(x)); return y;
}
__device__ __forceinline__ float lg2(float x) {
    float y; asm("lg2.approx.f32 %0, %1;" : "=f"(y) : "f"(x)); return y;
}
__device__ __forceinline__ ull pack2(float lo, float hi) {
    ull r; asm("mov.b64 %0, {%1, %2};" : "=l"(r) : "f"(lo), "f"(hi)); return r;
}
__device__ __forceinline__ void unpack2(ull v, float& lo, float& hi) {
    asm("mov.b64 {%0, %1}, %2;" : "=f"(lo), "=f"(hi) : "l"(v));
}
__device__ __forceinline__ ull subx2(ull a, ull b) {
    ull r; asm("sub.rn.f32x2 %0, %1, %2;" : "=l"(r) : "l"(a), "l"(b)); return r;
}
__device__ __forceinline__ ull addx2(ull a, ull b) {
    ull r; asm("add.rn.f32x2 %0, %1, %2;" : "=l"(r) : "l"(a), "l"(b)); return r;
}
__device__ __forceinline__ ull mulx2(ull a, ull b) {
    ull r; asm("mul.rn.f32x2 %0, %1, %2;" : "=l"(r) : "l"(a), "l"(b)); return r;
}
__device__ __forceinline__ ull fmax2p(ull a, ull b, ull c) {
    ull r; asm("fma.rn.f32x2 %0, %1, %2, %3;" : "=l"(r) : "l"(a), "l"(b), "l"(c)); return r;
}
// warp-wide f32 max via monotone-uint mapping + int redux (sm_80+)
__device__ __forceinline__ float warp_max_f32(float x) {
    unsigned b = __float_as_uint(x);
    unsigned k = (b & 0x80000000u) ? ~b : (b | 0x80000000u);
    unsigned m;
    asm("redux.sync.max.u32 %0, %1, 0xffffffff;" : "=r"(m) : "r"(k));
    unsigned r = (m & 0x80000000u) ? (m & 0x7fffffffu) : ~m;
    return __uint_as_float(r);
}

// ---------------------------------------------------------------------------
// Stage 0: zero plan accumulator AND d_out (harness poisons it; out_kernel
// accumulates with atomics). Graph replays -> must run every launch.
// ---------------------------------------------------------------------------
#define NZ_P   (BATCH * HDIM * HDIM / 4)   // 131072 float4
#define NZ_OUT (NTOK * HDIM / 4)           // 32768 float4
__global__ void zero_kernel(float* __restrict__ out) {
    int i = blockIdx.x * blockDim.x + threadIdx.x;
    float4 z = make_float4(0.f, 0.f, 0.f, 0.f);
    if (i < NZ_P) reinterpret_cast<float4*>(g_sumP)[i] = z;
    else          reinterpret_cast<float4*>(out)[i - NZ_P] = z;
}

// ---------------------------------------------------------------------------
// Stage 1: src[tok, h] = X[tok] . W[h] + b[h]   (4 tokens per CTA)
// ---------------------------------------------------------------------------
#define TPG 4
__global__ void __launch_bounds__(HDIM) src_kernel(
    const float* __restrict__ X, const float* __restrict__ W,
    const float* __restrict__ b)
{
    const int tok0 = blockIdx.x * TPG;
    __shared__ __align__(16) float xs[TPG][DSRC];   // 12 KB
    for (int idx = threadIdx.x; idx < TPG * DSRC; idx += HDIM)
        xs[idx / DSRC][idx % DSRC] = X[tok0 * DSRC + idx];
    __syncthreads();

    const int h = threadIdx.x;
    const float4* wr = reinterpret_cast<const float4*>(W + (size_t)h * DSRC);
    float acc0 = 0.f, acc1 = 0.f, acc2 = 0.f, acc3 = 0.f;
#pragma unroll 4
    for (int q = 0; q < DSRC / 4; q++) {
        float4 w4 = wr[q];
        float4 x0 = reinterpret_cast<const float4*>(xs[0])[q];
        float4 x1 = reinterpret_cast<const float4*>(xs[1])[q];
        float4 x2 = reinterpret_cast<const float4*>(xs[2])[q];
        float4 x3 = reinterpret_cast<const float4*>(xs[3])[q];
        acc0 = fmaf(w4.x, x0.x, acc0); acc0 = fmaf(w4.y, x0.y, acc0);
        acc0 = fmaf(w4.z, x0.z, acc0); acc0 = fmaf(w4.w, x0.w, acc0);
        acc1 = fmaf(w4.x, x1.x, acc1); acc1 = fmaf(w4.y, x1.y, acc1);
        acc1 = fmaf(w4.z, x1.z, acc1); acc1 = fmaf(w4.w, x1.w, acc1);
        acc2 = fmaf(w4.x, x2.x, acc2); acc2 = fmaf(w4.y, x2.y, acc2);
        acc2 = fmaf(w4.z, x2.z, acc2); acc2 = fmaf(w4.w, x2.w, acc2);
        acc3 = fmaf(w4.x, x3.x, acc3); acc3 = fmaf(w4.y, x3.y, acc3);
        acc3 = fmaf(w4.z, x3.z, acc3); acc3 = fmaf(w4.w, x3.w, acc3);
    }
    float bh = b[h];
    g_src[(tok0 + 0) * HDIM + h] = acc0 + bh;
    g_src[(tok0 + 1) * HDIM + h] = acc1 + bh;
    g_src[(tok0 + 2) * HDIM + h] = acc2 + bh;
    g_src[(tok0 + 3) * HDIM + h] = acc3 + bh;
}

// ---------------------------------------------------------------------------
// Binary search over a sorted float array (u-init only).
// ---------------------------------------------------------------------------
__device__ __forceinline__ int lboundf(const float* __restrict__ A, float x) {
    int lo = 0, hi = HDIM;
    while (lo < hi) { int m = (lo + hi) >> 1; if (A[m] < x) lo = m + 1; else hi = m; }
    return lo;
}

// ---------------------------------------------------------------------------
// One culled half-pass sum with packed f32x2 math.
// Q[p] = (x_{2p}, x_{2p+1}, dual_{2p}, dual_{2p+1}) for sorted positions.
// a = sum over qualifying elements of 2^( NEGC*(x - own)^2 + dual + sh ).
// Blocks of 32 sorted elements (16 pairs) are skipped when even their best
// case (block max dual, closest boundary distance) stays below -TW.
// ---------------------------------------------------------------------------
__device__ __forceinline__ float culled_sum(const float4* __restrict__ Q,
                                            const float2* __restrict__ blkRange,
                                            const float* __restrict__ blkMax,
                                            float own, float sh, ull negc2)
{
    const ull own2 = pack2(own, own);
    const ull sh2  = pack2(sh, sh);
    float a0 = 1e-30f, a1 = 0.f;
#pragma unroll 1
    for (int b = 0; b < NBLK; b++) {
        float2 rg = blkRange[b];
        float dd = fmaxf(fmaxf(rg.x - own, own - rg.y), 0.0f);
        if (fmaf(dd * dd, NEGC, blkMax[b] + sh) >= -TW) {
#pragma unroll
            for (int p = 16 * b; p < 16 * b + 16; p++) {
                float4 q = Q[p];
                ull X  = pack2(q.x, q.y);
                ull Yd = pack2(q.z, q.w);
                ull d  = subx2(X, own2);
                ull sq = mulx2(d, d);
                ull ys = addx2(Yd, sh2);
                ull e  = fmax2p(sq, negc2, ys);
                float el, eh; unpack2(e, el, eh);
                a0 += ex2(el);
                a1 += ex2(eh);
            }
        }
    }
    return a0 + a1;
}

// ---------------------------------------------------------------------------
// Stage 2: block-culled per-token base-2 log-domain Sinkhorn.
// s,t bitonic-sorted with index payloads; packed pair arrays for the inner
// loop (one LDS.128 per 2 elements, f32x2 arithmetic). Thread tid owns
// sorted row tid (t side, dual u) and sorted column tid (s side, dual v).
// Warp w == sorted block w; publishes blkMax (max dual) after each pass.
// Half-pass: own_dual -= lg2( culled_sum ) — shifted-LSE update (exact:
// shift = own_dual + 9 keeps all terms <= 0 after each normalization;
// nearest-neighbor u-init guarantees it at iteration 0 too).
// ---------------------------------------------------------------------------
__global__ void __launch_bounds__(512, 2) sinkhorn_kernel(
    const float* __restrict__ Y)
{
    const int tok  = blockIdx.x;
    const int bat  = tok >> 7;
    const int tid  = threadIdx.x;
    const int lane = tid & 31;
    const int warp = tid >> 5;

    __shared__ float sVal[HDIM], tVal[HDIM];      // sorted values
    __shared__ int   sIdx[HDIM], tIdx[HDIM];      // sorted pos -> original
    __shared__ __align__(16) float4 SQ[HDIM / 2]; // (s0,s1,v0,v1) pairs
    __shared__ __align__(16) float4 TQ[HDIM / 2]; // (t0,t1,u0,u1) pairs
    __shared__ float2 rgS[NBLK], rgT[NBLK];       // per-block (lo,hi) values
    __shared__ float blkMaxV[NBLK], blkMaxU[NBLK];

    sVal[tid] = g_src[tok * HDIM + tid];
    tVal[tid] = Y[tok * HDIM + tid];
    sIdx[tid] = tid;
    tIdx[tid] = tid;
    if (tid < NBLK) blkMaxV[tid] = 0.f;
    __syncthreads();

    // joint bitonic sort of s and t (values + index payloads)
    for (int k = 2; k <= HDIM; k <<= 1) {
        for (int j = k >> 1; j > 0; j >>= 1) {
            int ixj = tid ^ j;
            if (ixj > tid) {
                bool up = ((tid & k) == 0);
                float a = sVal[tid], b2 = sVal[ixj];
                if (up ? (a > b2) : (a < b2)) {
                    sVal[tid] = b2; sVal[ixj] = a;
                    int ti = sIdx[tid]; sIdx[tid] = sIdx[ixj]; sIdx[ixj] = ti;
                }
                float c = tVal[tid], d2 = tVal[ixj];
                if (up ? (c > d2) : (c < d2)) {
                    tVal[tid] = d2; tVal[ixj] = c;
                    int ti = tIdx[tid]; tIdx[tid] = tIdx[ixj]; tIdx[ixj] = ti;
                }
            }
            __syncthreads();
        }
    }

    // build packed pair arrays + block ranges
    if (tid < HDIM / 2) {
        SQ[tid] = make_float4(sVal[2 * tid], sVal[2 * tid + 1], 0.f, 0.f);
        TQ[tid] = make_float4(tVal[2 * tid], tVal[2 * tid + 1], 0.f, 0.f);
    }
    if (tid < NBLK) {
        rgS[tid] = make_float2(sVal[32 * tid], sVal[32 * tid + 31]);
        rgT[tid] = make_float2(tVal[32 * tid], tVal[32 * tid + 31]);
    }
    __syncthreads();

    const float t_own = tVal[tid];
    const float s_own = sVal[tid];
    const int   jorig = tIdx[tid];

    // init u via nearest sorted s neighbor: u = -9 + C*d_nn^2
    float u_own;
    {
        int p = lboundf(sVal, t_own);
        float dn = 3.402823466e+38f;
        if (p < HDIM) dn = fabsf(sVal[p] - t_own);
        if (p > 0)    dn = fminf(dn, fabsf(sVal[p - 1] - t_own));
        u_own = LOGMARG2 + CPOS * dn * dn;
    }
    float v_own = 0.f;

    const ull negc2 = pack2(NEGC, NEGC);
    float* SQ_s = reinterpret_cast<float*>(SQ);
    float* TQ_s = reinterpret_cast<float*>(TQ);
    const int own_slot = (tid >> 1) * 4 + 2 + (tid & 1);

    for (int it = 0; it < NITER; it++) {
        // ---- u-pass: culled sum over sorted s blocks ----
        u_own -= lg2(culled_sum(SQ, rgS, blkMaxV, t_own, u_own + 9.0f, negc2));
        TQ_s[own_slot] = u_own;
        if (lane == 0) {}  // keep structure simple
        {
            float m = warp_max_f32(u_own);
            if (lane == 0) blkMaxU[warp] = m;
        }
        __syncthreads();

        // ---- v-pass: culled sum over sorted t blocks ----
        v_own -= lg2(culled_sum(TQ, rgT, blkMaxU, s_own, v_own + 9.0f, negc2));
        SQ_s[own_slot] = v_own;
        {
            float m = warp_max_f32(v_own);
            if (lane == 0) blkMaxV[warp] = m;
        }
        __syncthreads();
    }

    // ---- Plan: P[jorig, iorig] = 2^(tau - 9), tau = -C d^2 + v + u + 9 ----
    {
        float* rowdst = g_sumP + (size_t)bat * HDIM * HDIM + (size_t)jorig * HDIM;
        const float sh = u_own + 9.0f;
        const ull own2 = pack2(t_own, t_own);
        const ull sh2  = pack2(sh, sh);
#pragma unroll 1
        for (int b = 0; b < NBLK; b++) {
            float2 rg = rgS[b];
            float dd = fmaxf(fmaxf(rg.x - t_own, t_own - rg.y), 0.0f);
            if (fmaf(dd * dd, NEGC, blkMaxV[b] + sh) >= -31.0f) {
#pragma unroll 4
                for (int p = 16 * b; p < 16 * b + 16; p++) {
                    float4 q = SQ[p];
                    ull X  = pack2(q.x, q.y);
                    ull Yd = pack2(q.z, q.w);
                    ull d  = subx2(X, own2);
                    ull sq = mulx2(d, d);
                    ull ys = addx2(Yd, sh2);
                    ull e  = fmax2p(sq, negc2, ys);
                    float el, eh; unpack2(e, el, eh);
                    if (el > -31.f) atomicAdd(rowdst + sIdx[2 * p],     ex2(el - 9.0f));
                    if (eh > -31.f) atomicAdd(rowdst + sIdx[2 * p + 1], ex2(eh - 9.0f));
                }
            }
        }
    }
}

// ---------------------------------------------------------------------------
// Stage 3: out[tok, k] += sum_{h in slice} src[tok,h]*(sumP[b,h,k]*2000
//                                                      + delta[h,k])
// Grid (16 token-groups of 16, 16 h-slices of 32). 256 CTAs, 256 threads.
// ---------------------------------------------------------------------------
#define OT_TOK 16
#define OT_H   32
__global__ void __launch_bounds__(256) out_kernel(
    const float* __restrict__ delta, float* __restrict__ out)
{
    const int tok0 = blockIdx.x * OT_TOK;
    const int h0   = blockIdx.y * OT_H;
    const int bat  = tok0 >> 7;       // OT_TOK divides SEQ -> no straddle
    const int k2   = threadIdx.x;     // float2 column index (0..255)

    __shared__ float sr[OT_TOK][OT_H];   // 2 KB
    for (int idx = threadIdx.x; idx < OT_TOK * OT_H; idx += 256)
        sr[idx / OT_H][idx % OT_H] = g_src[(tok0 + idx / OT_H) * HDIM + h0 + idx % OT_H];
    __syncthreads();

    const float2* P2 = reinterpret_cast<const float2*>(
        g_sumP + (size_t)bat * HDIM * HDIM);
    const float2* D2 = reinterpret_cast<const float2*>(delta);

    float a0[OT_TOK], a1[OT_TOK];
#pragma unroll
    for (int t = 0; t < OT_TOK; t++) { a0[t] = 0.f; a1[t] = 0.f; }

#pragma unroll 4
    for (int h = 0; h < OT_H; h++) {
        float2 p = __ldg(&P2[(h0 + h) * 256 + k2]);
        float2 d = __ldg(&D2[(h0 + h) * 256 + k2]);
        float pv0 = fmaf(p.x, 2000.0f, d.x);
        float pv1 = fmaf(p.y, 2000.0f, d.y);
#pragma unroll
        for (int t = 0; t < OT_TOK; t++) {
            float s = sr[t][h];
            a0[t] = fmaf(s, pv0, a0[t]);
            a1[t] = fmaf(s, pv1, a1[t]);
        }
    }
#pragma unroll
    for (int t = 0; t < OT_TOK; t++) {
        atomicAdd(&out[(tok0 + t) * HDIM + 2 * k2],     a0[t]);
        atomicAdd(&out[(tok0 + t) * HDIM + 2 * k2 + 1], a1[t]);
    }
}

// ---------------------------------------------------------------------------
extern "C" void kernel_launch(void* const* d_in, const int* in_sizes, int n_in,
                              void* d_out, int out_size)
{
    const float* X     = (const float*)d_in[0];  // (2,128,768)
    const float* Y     = (const float*)d_in[1];  // (2,128,512)
    const float* W     = (const float*)d_in[2];  // (512,768)
    const float* b     = (const float*)d_in[3];  // (512)
    const float* delta = (const float*)d_in[4];  // (512,512)
    float* out = (float*)d_out;                  // (2,128,512)

    zero_kernel<<<(NZ_P + NZ_OUT) / 256, 256>>>(out);
    src_kernel<<<NTOK / TPG, HDIM>>>(X, W, b);
    sinkhorn_kernel<<<NTOK, 512>>>(Y);
    dim3 ogrid(NTOK / OT_TOK, HDIM / OT_H);
    out_kernel<<<ogrid, 256>>>(delta, out);
}